// round 11
// baseline (speedup 1.0000x reference)
#include <cuda_runtime.h>
#include <math.h>

#define TT 32
#define DD 256
#define HH 768
#define GRIDN 128
#define NT 256

#define OFF_HXLAST (TT*128*HH)
#define OFF_PC     (OFF_HXLAST + 128*HH)
#define OFF_STEPS  (OFF_PC + 128)

#define WSTR_H 388   // 384 data ulls + pad per pair (whh buckets)
#define WSTR_I 132   // 128 data ulls + pad per pair (wih buckets)

typedef unsigned long long ull;

// persistent scratch (allocation-free rule)
__device__ float g_hxi[2][128][HH];               // double-buffered hidden state
__device__ float g_pd[8*128*32];                  // partial ponder dots [n][row][cg]
__device__ __align__(16) unsigned g_flags[GRIDN]; // barrier flags (monotonic)

struct SM {
  ull   whhA[12*WSTR_H];  // pair-packed weights, k%4 in {0,1}
  ull   whhB[12*WSTR_H];  // k%4 in {2,3}
  ull   wihA[12*WSTR_I];
  ull   wihB[12*WSTR_I];
  float hxn[32][26];
  float ahx[32][26];
  float wp[24];
  float ah[128], sc[128], spc[128], coef[128], pc[128];
  int   mask[128];
};

__device__ __forceinline__ ull fma2(ull a, ull b, ull c){
  ull d; asm("fma.rn.f32x2 %0,%1,%2,%3;" : "=l"(d) : "l"(a), "l"(b), "l"(c)); return d;
}
__device__ __forceinline__ ull add2(ull a, ull b){
  ull d; asm("add.rn.f32x2 %0,%1,%2;" : "=l"(d) : "l"(a), "l"(b)); return d;
}
__device__ __forceinline__ ull dup2(float x){
  ull d; unsigned r = __float_as_uint(x);
  asm("mov.b64 %0,{%1,%1};" : "=l"(d) : "r"(r)); return d;
}
__device__ __forceinline__ ull shx64(ull v, int m){
  unsigned lo = (unsigned)v, hi = (unsigned)(v >> 32);
  lo = __shfl_xor_sync(0xffffffffu, lo, m);
  hi = __shfl_xor_sync(0xffffffffu, hi, m);
  return ((ull)hi << 32) | lo;
}

// flag-based grid barrier with light backoff
__device__ __forceinline__ void gbar(unsigned ep){
  __syncthreads();
  if (threadIdx.x == 0)
    asm volatile("st.release.gpu.global.u32 [%0], %1;"
                 :: "l"(&g_flags[blockIdx.x]), "r"(ep) : "memory");
  if (threadIdx.x < 32){
    const unsigned* fp = g_flags + threadIdx.x*4;
    for(;;){
      unsigned a,b,c,d;
      asm volatile("ld.relaxed.gpu.global.v4.u32 {%0,%1,%2,%3}, [%4];"
                   : "=r"(a),"=r"(b),"=r"(c),"=r"(d) : "l"(fp) : "memory");
      if ((int)(a-ep)>=0 && (int)(b-ep)>=0 && (int)(c-ep)>=0 && (int)(d-ep)>=0) break;
      __nanosleep(64);
    }
    asm volatile("fence.acq_rel.gpu;" ::: "memory");
  }
  __syncthreads();
}

// GEMM: warp = 4 rows x 12 pairs (24 cols), lanes split K 32-way (contiguous
// float4 per lane). acc[a], a = r*12 + p. NIT = K/128 chunks. Depth-1 prefetch.
template<int NIT, int WSTR, bool CG>
__device__ __forceinline__ void gemmJ(ull (&acc)[48],
    const float* xrow0, int xstride,
    const ull* Wa, const ull* Wb, int lane)
{
  const float4* xq[4];
  #pragma unroll
  for (int r = 0; r < 4; r++) xq[r] = (const float4*)(xrow0 + r*xstride);

  float4 xc[4], xn[4];
  #pragma unroll
  for (int r = 0; r < 4; r++)
    xc[r] = CG ? __ldcg(xq[r] + lane) : __ldg(xq[r] + lane);

  #pragma unroll
  for (int it = 0; it < NIT; ++it){
    if (it + 1 < NIT){
      #pragma unroll
      for (int r = 0; r < 4; r++)
        xn[r] = CG ? __ldcg(xq[r] + (it+1)*32 + lane) : __ldg(xq[r] + (it+1)*32 + lane);
    }
    const int kofs = (it*32 + lane)*2;
    // jh = 0: k0,k0+1 from bucket A; jh = 1: k0+2,k0+3 from bucket B
    #pragma unroll
    for (int jh = 0; jh < 2; jh++){
      ull xd[8];
      #pragma unroll
      for (int r = 0; r < 4; r++){
        const float* xf = (const float*)&xc[r];
        xd[r*2+0] = dup2(xf[jh*2+0]);
        xd[r*2+1] = dup2(xf[jh*2+1]);
      }
      const ull* W = jh ? Wb : Wa;
      #pragma unroll
      for (int p = 0; p < 12; p++){
        ulonglong2 w = *(const ulonglong2*)(W + (size_t)p*WSTR + kofs);
        #pragma unroll
        for (int r = 0; r < 4; r++){
          acc[r*12+p] = fma2(xd[r*2+0], w.x, acc[r*12+p]);
          acc[r*12+p] = fma2(xd[r*2+1], w.y, acc[r*12+p]);
        }
      }
    }
    #pragma unroll
    for (int r = 0; r < 4; r++) xc[r] = xn[r];
  }
}

__device__ __forceinline__ void reduce48(ull (&acc)[48]){
  #pragma unroll
  for (int i = 0; i < 48; ++i){
    acc[i] = add2(acc[i], shx64(acc[i],16));
    acc[i] = add2(acc[i], shx64(acc[i],8));
    acc[i] = add2(acc[i], shx64(acc[i],4));
    acc[i] = add2(acc[i], shx64(acc[i],2));
    acc[i] = add2(acc[i], shx64(acc[i],1));
  }
}

__global__ void __launch_bounds__(NT, 1)
act_kernel(const float* __restrict__ input, const float* __restrict__ Wih,
           const float* __restrict__ Whh, const float* __restrict__ bih,
           const float* __restrict__ bhh, const float* __restrict__ wpv,
           const float* __restrict__ bpv, float* __restrict__ out)
{
  extern __shared__ unsigned char smraw[];
  SM& s = *reinterpret_cast<SM*>(smraw);
  const int tid = threadIdx.x, blk = blockIdx.x;
  const int rg = blk >> 5, cg = blk & 31;
  const int row0 = rg*32, col0 = cg*24;
  const int lane = tid & 31, warp = tid >> 5;
  const int r0w  = warp*4;           // warp's 4 local rows

  // ---- one-time: stage weights pair-packed into A/B buckets ----
  // bucket sel = (k>>1)&1 ; idx = p*WSTR + 2*(k>>2) + (k&1) ; float slot = c&1
  for (int idx = tid; idx < 24*HH; idx += NT){
    int c = idx / HH, k = idx - c*HH;
    int p = c >> 1;
    ull* base = ((k >> 1) & 1) ? s.whhB : s.whhA;
    size_t e = (size_t)p*WSTR_H + 2*(k>>2) + (k&1);
    ((float*)&base[e])[c & 1] = Whh[(size_t)(col0+c)*HH + k];
  }
  for (int idx = tid; idx < 24*DD; idx += NT){
    int c = idx / DD, k = idx - c*DD;
    int p = c >> 1;
    ull* base = ((k >> 1) & 1) ? s.wihB : s.wihA;
    size_t e = (size_t)p*WSTR_I + 2*(k>>2) + (k&1);
    ((float*)&base[e])[c & 1] = Wih[(size_t)(col0+c)*(DD+1) + k];
  }
  if (tid < 24) s.wp[tid] = wpv[col0+tid];
  if (tid < 128) s.pc[tid] = 0.f;
  for (int e = tid; e < 32*24; e += NT){
    int r2 = e/24, c2 = e - r2*24;
    g_hxi[0][row0+r2][col0+c2] = 0.f;
  }

  // epilogue lane (lane<24) registers: handles acc[lane] (row rrA) and
  // acc[lane+24] (row rrB = rrA+2), same column pair cc.
  int rrA = 0, rrB = 0, cc = 0;
  float flw0=0, flw1=0, bs0=0, bs1=0;
  if (lane < 24){
    int r = lane / 12, p = lane - r*12;
    rrA = r0w + r;
    rrB = rrA + 2;
    cc  = p*2;
    flw0 = Wih[(size_t)(col0+cc  )*(DD+1) + DD];
    flw1 = Wih[(size_t)(col0+cc+1)*(DD+1) + DD];
    bs0  = bih[col0+cc  ] + bhh[col0+cc  ];
    bs1  = bih[col0+cc+1] + bhh[col0+cc+1];
  }
  const float bp0 = bpv[0];
  int rb = 0;
  unsigned ep = g_flags[blk];   // epoch persists across graph replays
  gbar(++ep);

  for (int t = 0; t < TT; ++t){
    if (tid < 128){ s.ah[tid]=0.f; s.sc[tid]=0.f; s.spc[tid]=0.f; s.mask[tid]=1; }
    for (int e = tid; e < 32*24; e += NT){ int r2=e/24, c2=e-r2*24; s.ahx[r2][c2]=0.f; }
    __syncthreads();

    // ---- base = x_t @ W_ih^T + biases (reads input only; carry not needed) ----
    float baseA0=0, baseA1=0, baseB0=0, baseB1=0;
    {
      ull acc[48];
      #pragma unroll
      for (int i = 0; i < 48; i++) acc[i] = 0ull;
      gemmJ<2, WSTR_I, false>(acc, input + ((size_t)t*128 + row0 + r0w)*DD, DD,
                              s.wihA, s.wihB, lane);
      reduce48(acc);
      if (lane < 24){
        float2 fA = *(float2*)&acc[lane];
        float2 fB = *(float2*)&acc[lane+24];
        baseA0 = fA.x + bs0; baseA1 = fA.y + bs1;
        baseB0 = fB.x + bs0; baseB1 = fB.y + bs1;
      }
    }

    // barrier moved here: protects previous step's carry writes (and, for
    // t=0, the g_hxi zero-init). Base GEMM above overlaps the stragglers.
    gbar(++ep);

    // ---- ponder loop ----
    for (int n = 0; n < 8; ++n){
      ull acc[48];
      #pragma unroll
      for (int i = 0; i < 48; i++) acc[i] = 0ull;
      gemmJ<6, WSTR_H, true>(acc, &g_hxi[rb][row0 + r0w][0], HH,
                             s.whhA, s.whhB, lane);
      reduce48(acc);

      const float fl = (n == 0) ? 0.f : 1.f;
      if (lane < 24){
        float2 fA = *(float2*)&acc[lane];
        float2 fB = *(float2*)&acc[lane+24];
        float hA0 = tanhf(fA.x + baseA0 + fl*flw0);
        float hA1 = tanhf(fA.y + baseA1 + fl*flw1);
        float hB0 = tanhf(fB.x + baseB0 + fl*flw0);
        float hB1 = tanhf(fB.y + baseB1 + fl*flw1);
        s.hxn[rrA][cc]   = hA0; s.hxn[rrA][cc+1] = hA1;
        s.hxn[rrB][cc]   = hB0; s.hxn[rrB][cc+1] = hB1;
        int grA = row0 + rrA, grB = row0 + rrB, gc = col0 + cc;
        float2 oA, oB;
        if (s.mask[grA]) oA = make_float2(hA0, hA1);
        else             oA = __ldcg((const float2*)&g_hxi[rb][grA][gc]);
        if (s.mask[grB]) oB = make_float2(hB0, hB1);
        else             oB = __ldcg((const float2*)&g_hxi[rb][grB][gc]);
        *(float2*)&g_hxi[rb^1][grA][gc] = oA;
        *(float2*)&g_hxi[rb^1][grB][gc] = oB;
      }
      __syncthreads();
      if (tid < 32){
        float pd = 0.f;
        #pragma unroll
        for (int c = 0; c < 24; c++) pd = fmaf(s.hxn[tid][c], s.wp[c], pd);
        g_pd[(size_t)(n*128 + row0 + tid)*32 + cg] = pd;
      }
      gbar(++ep);

      // redundant identical scalar update (fixed order => identical everywhere)
      int nm = 0;
      if (tid < 128){
        const float4* pr4 = (const float4*)&g_pd[(size_t)(n*128 + tid)*32];
        float sum = 0.f;
        #pragma unroll
        for (int q = 0; q < 8; q++){
          float4 v4 = __ldcg(pr4 + q);
          sum += v4.x; sum += v4.y; sum += v4.z; sum += v4.w;
        }
        float h = 1.f/(1.f + expf(-(sum + bp0)));
        int   m  = s.mask[tid];
        float mf = m ? 1.f : 0.f;
        if (m) s.spc[tid] = -s.ah[tid];
        float ah2 = s.ah[tid] + mf*h;
        float p2  = h - fmaxf(ah2 - 1.f, 0.f);
        s.coef[tid] = mf*(1.f + p2);
        s.sc[tid]  += mf;
        s.ah[tid]   = ah2;
        int m2 = (ah2 < 0.99f);
        s.mask[tid] = m2;
        nm = m2;
      }
      int nlive = __syncthreads_or(nm);
      for (int e = tid; e < 32*24; e += NT){
        int r2 = e/24, c2 = e - r2*24;
        s.ahx[r2][c2] = fmaf(s.coef[row0+r2], s.hxn[r2][c2], s.ahx[r2][c2]);
      }
      __syncthreads();
      rb ^= 1;
      if (!nlive) break;
    }

    // ---- end of step: outputs + carry (no barrier here; next step's
    //      post-base gbar protects the carry exchange) ----
    for (int e = tid; e < 32*24; e += NT){
      int r2 = e/24, c2 = e - r2*24;
      int gr2 = row0 + r2, gc2 = col0 + c2;
      float v = s.ahx[r2][c2] / s.sc[gr2];
      out[(size_t)(t*128 + gr2)*HH + gc2] = v;
      if (t == TT-1) out[OFF_HXLAST + (size_t)gr2*HH + gc2] = v;
      g_hxi[rb][gr2][gc2] = v;
    }
    if (blk == 0 && tid < 128){
      s.pc[tid] += s.spc[tid];
      out[OFF_STEPS + t*128 + tid] = s.sc[tid];
    }
  }

  if (blk == 0 && tid < 128) out[OFF_PC + tid] = s.pc[tid];
}

extern "C" void kernel_launch(void* const* d_in, const int* in_sizes, int n_in,
                              void* d_out, int out_size)
{
  const float* input = (const float*)d_in[0];
  const float* Wih   = (const float*)d_in[1];
  const float* Whh   = (const float*)d_in[2];
  const float* bih   = (const float*)d_in[3];
  const float* bhh   = (const float*)d_in[4];
  const float* wpv   = (const float*)d_in[5];
  const float* bpv   = (const float*)d_in[6];
  (void)in_sizes; (void)n_in; (void)out_size;

  cudaFuncSetAttribute(act_kernel, cudaFuncAttributeMaxDynamicSharedMemorySize, (int)sizeof(SM));
  act_kernel<<<GRIDN, NT, sizeof(SM)>>>(input, Wih, Whh, bih, bhh, wpv, bpv, (float*)d_out);
}

// round 12
// speedup vs baseline: 3.6021x; 3.6021x over previous
#include <cuda_runtime.h>
#include <math.h>

#define TT 32
#define DD 256
#define HH 768
#define GRIDN 128
#define NT 256

#define OFF_HXLAST (TT*128*HH)
#define OFF_PC     (OFF_HXLAST + 128*HH)
#define OFF_STEPS  (OFF_PC + 128)

// persistent scratch (allocation-free rule)
__device__ float g_hxi[2][128][HH];               // double-buffered hidden state
__device__ float g_pd[8*128*32];                  // partial ponder dots [n][row][cg]
__device__ __align__(16) unsigned g_flags[GRIDN]; // barrier flags (monotonic)

struct SM {
  float whh[24][HH];     // W_hh rows for this block's 24 cols (73728 B)
  float wih[24][260];    // W_ih rows, k<256 (+pad)           (24960 B)
  float base[32][26];    // x@Wih^T + bias per step
  float hxn[32][26];     // hx_new tile
  float ahx[32][26];     // accum_hx tile
  float flagw[24];
  float wp[24];
  float bias[24];
  float ah[32], sc[32], spc[32], coef[32], pc[32];
  int   mask[32];
};

// group-scoped flag barrier: 32 blocks of this row group only
__device__ __forceinline__ void gbar(unsigned ep, int rg){
  __syncthreads();
  if (threadIdx.x == 0)
    asm volatile("st.release.gpu.global.u32 [%0], %1;"
                 :: "l"(&g_flags[blockIdx.x]), "r"(ep) : "memory");
  if (threadIdx.x < 8){
    const unsigned* fp = g_flags + rg*32 + threadIdx.x*4;
    for(;;){
      unsigned a,b,c,d;
      asm volatile("ld.relaxed.gpu.global.v4.u32 {%0,%1,%2,%3}, [%4];"
                   : "=r"(a),"=r"(b),"=r"(c),"=r"(d) : "l"(fp) : "memory");
      if ((int)(a-ep)>=0 && (int)(b-ep)>=0 && (int)(c-ep)>=0 && (int)(d-ep)>=0) break;
      __nanosleep(64);
    }
    asm volatile("fence.acq_rel.gpu;" ::: "memory");
  }
  __syncthreads();
}

// R2-style GEMM: warp = 4 rows x 24 cols, lanes split K (contiguous float4/lane).
// W rows: [c][k] with row stride WS floats. Depth-1 prefetch. 2304 FFMA/thread @NIT=6.
template<int NIT, int WS, bool CG>
__device__ __forceinline__ void gemmR2(float (&acc)[4][24],
    const float* xrow0, int xstride, const float* W, int lane)
{
  const float4* xq[4];
  #pragma unroll
  for (int r = 0; r < 4; r++) xq[r] = (const float4*)(xrow0 + r*xstride);

  float4 xv[4], xn[4];
  #pragma unroll
  for (int r = 0; r < 4; r++)
    xv[r] = CG ? __ldcg(xq[r] + lane) : __ldg(xq[r] + lane);

  #pragma unroll
  for (int it = 0; it < NIT; ++it){
    if (it + 1 < NIT){
      #pragma unroll
      for (int r = 0; r < 4; r++)
        xn[r] = CG ? __ldcg(xq[r] + (it+1)*32 + lane) : __ldg(xq[r] + (it+1)*32 + lane);
    }
    const int kb = (it*32 + lane)*4;
    #pragma unroll
    for (int c = 0; c < 24; ++c){
      float4 w = *(const float4*)&W[c*WS + kb];
      #pragma unroll
      for (int r = 0; r < 4; ++r){
        acc[r][c] = fmaf(xv[r].x, w.x, acc[r][c]);
        acc[r][c] = fmaf(xv[r].y, w.y, acc[r][c]);
        acc[r][c] = fmaf(xv[r].z, w.z, acc[r][c]);
        acc[r][c] = fmaf(xv[r].w, w.w, acc[r][c]);
      }
    }
    #pragma unroll
    for (int r = 0; r < 4; ++r) xv[r] = xn[r];
  }
}

// 5-level butterfly over 96 accs; lane keeps vals[s] for i = lane + 32s
__device__ __forceinline__ void reduce96(float (&acc)[4][24], float (&vals)[3], int lane){
  #pragma unroll
  for (int r = 0; r < 4; ++r){
    #pragma unroll
    for (int c = 0; c < 24; ++c){
      float v = acc[r][c];
      v += __shfl_xor_sync(0xffffffffu, v, 16);
      v += __shfl_xor_sync(0xffffffffu, v, 8);
      v += __shfl_xor_sync(0xffffffffu, v, 4);
      v += __shfl_xor_sync(0xffffffffu, v, 2);
      v += __shfl_xor_sync(0xffffffffu, v, 1);
      const int i = r*24 + c;
      if (lane == (i & 31)) vals[i >> 5] = v;
    }
  }
}

__global__ void __launch_bounds__(NT, 1)
act_kernel(const float* __restrict__ input, const float* __restrict__ Wih,
           const float* __restrict__ Whh, const float* __restrict__ bih,
           const float* __restrict__ bhh, const float* __restrict__ wpv,
           const float* __restrict__ bpv, float* __restrict__ out)
{
  extern __shared__ unsigned char smraw[];
  SM& s = *reinterpret_cast<SM*>(smraw);
  const int tid = threadIdx.x, blk = blockIdx.x;
  const int rg = blk >> 5, cg = blk & 31;
  const int row0 = rg*32, col0 = cg*24;
  const int lane = tid & 31, warp = tid >> 5;
  const int r0w  = warp*4;

  // ---- one-time: stage weights ----
  for (int idx = tid; idx < 24*HH; idx += NT){
    int c = idx / HH, k = idx - c*HH;
    s.whh[c][k] = Whh[(size_t)(col0+c)*HH + k];
  }
  for (int idx = tid; idx < 24*DD; idx += NT){
    int c = idx / DD, k = idx - c*DD;
    s.wih[c][k] = Wih[(size_t)(col0+c)*(DD+1) + k];
  }
  if (tid < 24){
    s.flagw[tid] = Wih[(size_t)(col0+tid)*(DD+1) + DD];
    s.wp[tid]    = wpv[col0+tid];
    s.bias[tid]  = bih[col0+tid] + bhh[col0+tid];
  }
  if (tid < 32) s.pc[tid] = 0.f;
  for (int e = tid; e < 32*24; e += NT){
    int r2 = e/24, c2 = e - r2*24;
    g_hxi[0][row0+r2][col0+c2] = 0.f;
  }
  const float bp0 = bpv[0];
  int rb = 0;
  unsigned ep = g_flags[blk];   // epoch persists across graph replays

  for (int t = 0; t < TT; ++t){
    if (tid < 32){ s.ah[tid]=0.f; s.sc[tid]=0.f; s.spc[tid]=0.f; s.mask[tid]=1; }
    for (int e = tid; e < 32*24; e += NT){ int r2=e/24, c2=e-r2*24; s.ahx[r2][c2]=0.f; }
    __syncthreads();

    // ---- base = x_t @ W_ih^T + biases (reads input only) ----
    {
      float acc[4][24];
      #pragma unroll
      for (int r = 0; r < 4; r++)
        #pragma unroll
        for (int c = 0; c < 24; c++) acc[r][c] = 0.f;
      gemmR2<2, 260, false>(acc, input + ((size_t)t*128 + row0 + r0w)*DD, DD,
                            &s.wih[0][0], lane);
      float vals[3];
      reduce96(acc, vals, lane);
      #pragma unroll
      for (int q = 0; q < 3; ++q){
        const int i = lane + 32*q;
        const int r = i / 24, c = i - r*24;
        s.base[r0w + r][c] = vals[q] + s.bias[c];
      }
    }

    // group barrier: protects previous step's carry (t=0: the zero-init)
    gbar(++ep, rg);

    // ---- ponder loop (group-local halting) ----
    for (int n = 0; n < 8; ++n){
      float acc[4][24];
      #pragma unroll
      for (int r = 0; r < 4; r++)
        #pragma unroll
        for (int c = 0; c < 24; c++) acc[r][c] = 0.f;
      gemmR2<6, HH, true>(acc, &g_hxi[rb][row0 + r0w][0], HH,
                          &s.whh[0][0], lane);
      float vals[3];
      reduce96(acc, vals, lane);

      const float fl = (n == 0) ? 0.f : 1.f;
      #pragma unroll
      for (int q = 0; q < 3; ++q){
        const int i = lane + 32*q;
        const int r = i / 24, c = i - r*24;
        const int rr = r0w + r;
        float h = tanhf(vals[q] + s.base[rr][c] + fl*s.flagw[c]);
        s.hxn[rr][c] = h;
        int gr = row0 + rr, gc = col0 + c;
        float o = s.mask[rr] ? h : __ldcg(&g_hxi[rb][gr][gc]);
        g_hxi[rb^1][gr][gc] = o;
      }
      __syncthreads();
      if (tid < 32){
        float pd = 0.f;
        #pragma unroll
        for (int c = 0; c < 24; c++) pd = fmaf(s.hxn[tid][c], s.wp[c], pd);
        g_pd[(size_t)(n*128 + row0 + tid)*32 + cg] = pd;
      }
      gbar(++ep, rg);

      // redundant identical scalar update within group (fixed order)
      int nm = 0;
      if (tid < 32){
        const float4* pr4 = (const float4*)&g_pd[(size_t)(n*128 + row0 + tid)*32];
        float sum = 0.f;
        #pragma unroll
        for (int q = 0; q < 8; q++){
          float4 v4 = __ldcg(pr4 + q);
          sum += v4.x; sum += v4.y; sum += v4.z; sum += v4.w;
        }
        float h = 1.f/(1.f + expf(-(sum + bp0)));
        int   m  = s.mask[tid];
        float mf = m ? 1.f : 0.f;
        if (m) s.spc[tid] = -s.ah[tid];
        float ah2 = s.ah[tid] + mf*h;
        float p2  = h - fmaxf(ah2 - 1.f, 0.f);
        s.coef[tid] = mf*(1.f + p2);
        s.sc[tid]  += mf;
        s.ah[tid]   = ah2;
        int m2 = (ah2 < 0.99f);
        s.mask[tid] = m2;
        nm = m2;
      }
      int nlive = __syncthreads_or(nm);
      for (int e = tid; e < 32*24; e += NT){
        int r2 = e/24, c2 = e - r2*24;
        s.ahx[r2][c2] = fmaf(s.coef[r2], s.hxn[r2][c2], s.ahx[r2][c2]);
      }
      __syncthreads();
      rb ^= 1;
      if (!nlive) break;
    }

    // ---- end of step: outputs + carry (next step's post-base gbar protects) ----
    for (int e = tid; e < 32*24; e += NT){
      int r2 = e/24, c2 = e - r2*24;
      int gr2 = row0 + r2, gc2 = col0 + c2;
      float v = s.ahx[r2][c2] / s.sc[r2];
      out[(size_t)(t*128 + gr2)*HH + gc2] = v;
      if (t == TT-1) out[OFF_HXLAST + (size_t)gr2*HH + gc2] = v;
      g_hxi[rb][gr2][gc2] = v;
    }
    if (cg == 0 && tid < 32){
      s.pc[tid] += s.spc[tid];
      out[OFF_STEPS + t*128 + row0 + tid] = s.sc[tid];
    }
  }

  if (cg == 0 && tid < 32) out[OFF_PC + row0 + tid] = s.pc[tid];
}

extern "C" void kernel_launch(void* const* d_in, const int* in_sizes, int n_in,
                              void* d_out, int out_size)
{
  const float* input = (const float*)d_in[0];
  const float* Wih   = (const float*)d_in[1];
  const float* Whh   = (const float*)d_in[2];
  const float* bih   = (const float*)d_in[3];
  const float* bhh   = (const float*)d_in[4];
  const float* wpv   = (const float*)d_in[5];
  const float* bpv   = (const float*)d_in[6];
  (void)in_sizes; (void)n_in; (void)out_size;

  cudaFuncSetAttribute(act_kernel, cudaFuncAttributeMaxDynamicSharedMemorySize, (int)sizeof(SM));
  act_kernel<<<GRIDN, NT, sizeof(SM)>>>(input, Wih, Whh, bih, bhh, wpv, bpv, (float*)d_out);
}

// round 13
// speedup vs baseline: 3.9877x; 1.1071x over previous
#include <cuda_runtime.h>
#include <math.h>

#define TT 32
#define DD 256
#define HH 768
#define GRIDN 128
#define NT 256

#define OFF_HXLAST (TT*128*HH)
#define OFF_PC     (OFF_HXLAST + 128*HH)
#define OFF_STEPS  (OFF_PC + 128)

// persistent scratch (allocation-free rule)
__device__ float g_hxi[2][128][HH];               // double-buffered hidden state
__device__ float g_pd[8*128*32];                  // partial ponder dots [n][row][cg]
__device__ __align__(16) unsigned g_flags[GRIDN]; // barrier flags (monotonic)

struct SM {
  float whh[24][HH];     // W_hh rows for this block's 24 cols (73728 B)
  float wih[24][260];    // W_ih rows, k<256 (+pad)           (24960 B)
  float base[32][26];    // x@Wih^T + bias per step
  float hxn[32][26];     // hx_new tile
  float ahx[32][26];     // accum_hx tile
  float flagw[24];
  float wp[24];
  float bias[24];
  float ah[32], sc[32], spc[32], coef[32], pc[32];
  int   mask[32];
};

// group-scoped flag barrier: 32 blocks of this row group only
__device__ __forceinline__ void gbar(unsigned ep, int rg){
  __syncthreads();
  if (threadIdx.x == 0)
    asm volatile("st.release.gpu.global.u32 [%0], %1;"
                 :: "l"(&g_flags[blockIdx.x]), "r"(ep) : "memory");
  if (threadIdx.x < 8){
    const unsigned* fp = g_flags + rg*32 + threadIdx.x*4;
    for(;;){
      unsigned a,b,c,d;
      asm volatile("ld.relaxed.gpu.global.v4.u32 {%0,%1,%2,%3}, [%4];"
                   : "=r"(a),"=r"(b),"=r"(c),"=r"(d) : "l"(fp) : "memory");
      if ((int)(a-ep)>=0 && (int)(b-ep)>=0 && (int)(c-ep)>=0 && (int)(d-ep)>=0) break;
      __nanosleep(64);
    }
    asm volatile("fence.acq_rel.gpu;" ::: "memory");
  }
  __syncthreads();
}

// GEMM: warp = 4 rows x 24 cols as 2 column-halves (ch) x K-split 16 (kl).
// lane = ch*16 + kl. Per thread: acc[4][12], 2304 FFMA, 144 LDS.128, 48 LDG.128.
// W rows: [c][k], row stride WS floats. Depth-1 prefetch.
template<int NIT, int WS, bool CG>
__device__ __forceinline__ void gemm16(float (&acc)[4][12],
    const float* xrow0, int xstride, const float* W, int kl, int ch)
{
  const float4* xq[4];
  #pragma unroll
  for (int r = 0; r < 4; r++) xq[r] = (const float4*)(xrow0 + r*xstride);

  float4 xv[4], xn[4];
  #pragma unroll
  for (int r = 0; r < 4; r++)
    xv[r] = CG ? __ldcg(xq[r] + kl) : __ldg(xq[r] + kl);

  const float* Wc = W + ch*12*WS;

  #pragma unroll
  for (int it = 0; it < NIT; ++it){
    if (it + 1 < NIT){
      #pragma unroll
      for (int r = 0; r < 4; r++)
        xn[r] = CG ? __ldcg(xq[r] + (it+1)*16 + kl) : __ldg(xq[r] + (it+1)*16 + kl);
    }
    const int kb = (it*16 + kl)*4;
    #pragma unroll
    for (int c = 0; c < 12; ++c){
      float4 w = *(const float4*)&Wc[c*WS + kb];
      #pragma unroll
      for (int r = 0; r < 4; ++r){
        acc[r][c] = fmaf(xv[r].x, w.x, acc[r][c]);
        acc[r][c] = fmaf(xv[r].y, w.y, acc[r][c]);
        acc[r][c] = fmaf(xv[r].z, w.z, acc[r][c]);
        acc[r][c] = fmaf(xv[r].w, w.w, acc[r][c]);
      }
    }
    #pragma unroll
    for (int r = 0; r < 4; ++r) xv[r] = xn[r];
  }
}

// 4-level butterfly over kl (within each 16-lane ch group); 48 accs,
// lane kl keeps vals[q] for i = kl + 16q (r = i/12, c_local = i%12).
__device__ __forceinline__ void reduce48(float (&acc)[4][12], float (&vals)[3], int kl){
  #pragma unroll
  for (int r = 0; r < 4; ++r){
    #pragma unroll
    for (int c = 0; c < 12; ++c){
      float v = acc[r][c];
      v += __shfl_xor_sync(0xffffffffu, v, 8);
      v += __shfl_xor_sync(0xffffffffu, v, 4);
      v += __shfl_xor_sync(0xffffffffu, v, 2);
      v += __shfl_xor_sync(0xffffffffu, v, 1);
      const int i = r*12 + c;
      if (kl == (i & 15)) vals[i >> 4] = v;
    }
  }
}

__global__ void __launch_bounds__(NT, 1)
act_kernel(const float* __restrict__ input, const float* __restrict__ Wih,
           const float* __restrict__ Whh, const float* __restrict__ bih,
           const float* __restrict__ bhh, const float* __restrict__ wpv,
           const float* __restrict__ bpv, float* __restrict__ out)
{
  extern __shared__ unsigned char smraw[];
  SM& s = *reinterpret_cast<SM*>(smraw);
  const int tid = threadIdx.x, blk = blockIdx.x;
  const int rg = blk >> 5, cg = blk & 31;
  const int row0 = rg*32, col0 = cg*24;
  const int lane = tid & 31, warp = tid >> 5;
  const int kl = lane & 15, ch = lane >> 4;
  const int r0w  = warp*4;

  // ---- one-time: stage weights ----
  for (int idx = tid; idx < 24*HH; idx += NT){
    int c = idx / HH, k = idx - c*HH;
    s.whh[c][k] = Whh[(size_t)(col0+c)*HH + k];
  }
  for (int idx = tid; idx < 24*DD; idx += NT){
    int c = idx / DD, k = idx - c*DD;
    s.wih[c][k] = Wih[(size_t)(col0+c)*(DD+1) + k];
  }
  if (tid < 24){
    s.flagw[tid] = Wih[(size_t)(col0+tid)*(DD+1) + DD];
    s.wp[tid]    = wpv[col0+tid];
    s.bias[tid]  = bih[col0+tid] + bhh[col0+tid];
  }
  if (tid < 32) s.pc[tid] = 0.f;
  for (int e = tid; e < 32*24; e += NT){
    int r2 = e/24, c2 = e - r2*24;
    g_hxi[0][row0+r2][col0+c2] = 0.f;
  }
  const float bp0 = bpv[0];
  int rb = 0;
  unsigned ep = g_flags[blk];   // epoch persists across graph replays

  for (int t = 0; t < TT; ++t){
    if (tid < 32){ s.ah[tid]=0.f; s.sc[tid]=0.f; s.spc[tid]=0.f; s.mask[tid]=1; }
    for (int e = tid; e < 32*24; e += NT){ int r2=e/24, c2=e-r2*24; s.ahx[r2][c2]=0.f; }
    __syncthreads();

    // ---- base = x_t @ W_ih^T + biases (reads input only) ----
    {
      float acc[4][12];
      #pragma unroll
      for (int r = 0; r < 4; r++)
        #pragma unroll
        for (int c = 0; c < 12; c++) acc[r][c] = 0.f;
      gemm16<4, 260, false>(acc, input + ((size_t)t*128 + row0 + r0w)*DD, DD,
                            &s.wih[0][0], kl, ch);
      float vals[3];
      reduce48(acc, vals, kl);
      #pragma unroll
      for (int q = 0; q < 3; ++q){
        const int i = kl + 16*q;
        const int r = i / 12, cl = i - r*12;
        const int c = ch*12 + cl;
        s.base[r0w + r][c] = vals[q] + s.bias[c];
      }
    }

    // group barrier: protects previous step's carry (t=0: the zero-init)
    gbar(++ep, rg);

    // ---- ponder loop (group-local halting) ----
    for (int n = 0; n < 8; ++n){
      float acc[4][12];
      #pragma unroll
      for (int r = 0; r < 4; r++)
        #pragma unroll
        for (int c = 0; c < 12; c++) acc[r][c] = 0.f;
      gemm16<12, HH, true>(acc, &g_hxi[rb][row0 + r0w][0], HH,
                           &s.whh[0][0], kl, ch);
      float vals[3];
      reduce48(acc, vals, kl);

      const float fl = (n == 0) ? 0.f : 1.f;
      #pragma unroll
      for (int q = 0; q < 3; ++q){
        const int i = kl + 16*q;
        const int r = i / 12, cl = i - r*12;
        const int c = ch*12 + cl;
        const int rr = r0w + r;
        float h = tanhf(vals[q] + s.base[rr][c] + fl*s.flagw[c]);
        s.hxn[rr][c] = h;
        int gr = row0 + rr, gc = col0 + c;
        float o = s.mask[rr] ? h : __ldcg(&g_hxi[rb][gr][gc]);
        g_hxi[rb^1][gr][gc] = o;
      }
      __syncthreads();
      if (tid < 32){
        float pd = 0.f;
        #pragma unroll
        for (int c = 0; c < 24; c++) pd = fmaf(s.hxn[tid][c], s.wp[c], pd);
        g_pd[(size_t)(n*128 + row0 + tid)*32 + cg] = pd;
      }
      gbar(++ep, rg);

      // redundant identical scalar update within group (fixed order)
      int nm = 0;
      if (tid < 32){
        const float4* pr4 = (const float4*)&g_pd[(size_t)(n*128 + row0 + tid)*32];
        float sum = 0.f;
        #pragma unroll
        for (int q = 0; q < 8; q++){
          float4 v4 = __ldcg(pr4 + q);
          sum += v4.x; sum += v4.y; sum += v4.z; sum += v4.w;
        }
        float h = 1.f/(1.f + expf(-(sum + bp0)));
        int   m  = s.mask[tid];
        float mf = m ? 1.f : 0.f;
        if (m) s.spc[tid] = -s.ah[tid];
        float ah2 = s.ah[tid] + mf*h;
        float p2  = h - fmaxf(ah2 - 1.f, 0.f);
        s.coef[tid] = mf*(1.f + p2);
        s.sc[tid]  += mf;
        s.ah[tid]   = ah2;
        int m2 = (ah2 < 0.99f);
        s.mask[tid] = m2;
        nm = m2;
      }
      int nlive = __syncthreads_or(nm);
      for (int e = tid; e < 32*24; e += NT){
        int r2 = e/24, c2 = e - r2*24;
        s.ahx[r2][c2] = fmaf(s.coef[r2], s.hxn[r2][c2], s.ahx[r2][c2]);
      }
      __syncthreads();
      rb ^= 1;
      if (!nlive) break;
    }

    // ---- end of step: outputs + carry (next step's post-base gbar protects) ----
    for (int e = tid; e < 32*24; e += NT){
      int r2 = e/24, c2 = e - r2*24;
      int gr2 = row0 + r2, gc2 = col0 + c2;
      float v = s.ahx[r2][c2] / s.sc[r2];
      out[(size_t)(t*128 + gr2)*HH + gc2] = v;
      if (t == TT-1) out[OFF_HXLAST + (size_t)gr2*HH + gc2] = v;
      g_hxi[rb][gr2][gc2] = v;
    }
    if (cg == 0 && tid < 32){
      s.pc[tid] += s.spc[tid];
      out[OFF_STEPS + t*128 + row0 + tid] = s.sc[tid];
    }
  }

  if (cg == 0 && tid < 32) out[OFF_PC + row0 + tid] = s.pc[tid];
}

extern "C" void kernel_launch(void* const* d_in, const int* in_sizes, int n_in,
                              void* d_out, int out_size)
{
  const float* input = (const float*)d_in[0];
  const float* Wih   = (const float*)d_in[1];
  const float* Whh   = (const float*)d_in[2];
  const float* bih   = (const float*)d_in[3];
  const float* bhh   = (const float*)d_in[4];
  const float* wpv   = (const float*)d_in[5];
  const float* bpv   = (const float*)d_in[6];
  (void)in_sizes; (void)n_in; (void)out_size;

  cudaFuncSetAttribute(act_kernel, cudaFuncAttributeMaxDynamicSharedMemorySize, (int)sizeof(SM));
  act_kernel<<<GRIDN, NT, sizeof(SM)>>>(input, Wih, Whh, bih, bhh, wpv, bpv, (float*)d_out);
}